// round 2
// baseline (speedup 1.0000x reference)
#include <cuda_runtime.h>
#include <math.h>

#define NN 100000
#define DD 128
#define TM 128

typedef unsigned long long ull;

// Scratch (device globals — no allocation allowed)
__device__ __align__(16) float g_sum[(size_t)NN * DD];
__device__ __align__(16) float g_cnt[NN];
__device__ __align__(16) float g_x1[(size_t)NN * DD];

// ---------------------------------------------------------------------------
// packed fp32x2 helpers (sm_103a FFMA2 — only reachable via PTX fma.rn.f32x2)
// ---------------------------------------------------------------------------
__device__ __forceinline__ ull pack2(float lo, float hi) {
    ull r;
    asm("mov.b64 %0, {%1, %2};" : "=l"(r) : "f"(lo), "f"(hi));
    return r;
}
__device__ __forceinline__ void fma2(ull& d, ull a, ull b) {
    asm("fma.rn.f32x2 %0, %1, %2, %3;" : "=l"(d) : "l"(a), "l"(b), "l"(d));
}
__device__ __forceinline__ float2 unpack2(ull v) {
    float2 f;
    asm("mov.b64 {%0, %1}, %2;" : "=f"(f.x), "=f"(f.y) : "l"(v));
    return f;
}

// ---------------------------------------------------------------------------
// Edge scatter: one warp per edge. Gather 512B row of x[src], vector-red-add
// into sum[dst], count edges per dst.
// ---------------------------------------------------------------------------
__global__ void scatter_kernel(const float* __restrict__ x,
                               const int* __restrict__ ei, int E,
                               float* __restrict__ sum, float* __restrict__ cnt)
{
    long long gt = (long long)blockIdx.x * blockDim.x + threadIdx.x;
    int e = (int)(gt >> 5);
    if (e >= E) return;
    int lane = threadIdx.x & 31;
    int src = ei[e];
    int dst = ei[E + e];
    float4 v = *(const float4*)(x + (size_t)src * DD + lane * 4);
    float* p = sum + (size_t)dst * DD + lane * 4;
    asm volatile("red.global.add.v4.f32 [%0], {%1,%2,%3,%4};"
                 :: "l"(p), "f"(v.x), "f"(v.y), "f"(v.z), "f"(v.w)
                 : "memory");
    if (lane == 0) atomicAdd(cnt + dst, 1.0f);
}

// ---------------------------------------------------------------------------
// Fused per-layer GEMM: out[i,:] = act( (sum[i,:]/max(cnt,1)) @ Wl^T
//                                       + x[i,:] @ Wr^T + b )
// Block: 128 rows x 128 cols, 512 threads, 4x8 microtile per thread.
// Inner product via packed fma.rn.f32x2 (2 FLOPs per FMA-pipe issue).
// smem: Wt[256][128] (transposed concat of Wl,Wr) + swizzled A tile (float4).
// ---------------------------------------------------------------------------
__global__ void __launch_bounds__(512, 1) fused_kernel(
    const float* __restrict__ x,
    const float* __restrict__ sum,
    const float* __restrict__ cnt,
    const float* __restrict__ wl,
    const float* __restrict__ wr,
    const float* __restrict__ bias,
    float* __restrict__ out,
    int n_nodes, int do_gelu)
{
    extern __shared__ float smem[];
    float*  Wt  = smem;                         // 256*128 floats = 128KB
    float4* As4 = (float4*)(smem + 256 * 128);  // 128*32 float4 = 64KB (swizzled)

    const int tid = threadIdx.x;
    const int tx = tid & 15;      // n: 8 cols each (as 4 f32x2 pairs)
    const int ty = tid >> 4;      // m: 0..31, rows ty + 32*i
    const int row0 = blockIdx.x * TM;

    // ---- Load both weight matrices transposed into smem: Wt[k][n] = W[n][k].
    {
        const int nb = (tid & 31) * 4;   // n block of 4
        const int kb = tid >> 5;         // 0..15
        #pragma unroll
        for (int mat = 0; mat < 2; mat++) {
            const float* W = mat ? wr : wl;
            float* WtM = Wt + mat * 128 * 128;
            #pragma unroll
            for (int it = 0; it < 2; it++) {
                int k4 = kb + 16 * it;   // float4 chunk along k: 0..31
                float4 r0 = *(const float4*)(W + (size_t)(nb + 0) * 128 + k4 * 4);
                float4 r1 = *(const float4*)(W + (size_t)(nb + 1) * 128 + k4 * 4);
                float4 r2 = *(const float4*)(W + (size_t)(nb + 2) * 128 + k4 * 4);
                float4 r3 = *(const float4*)(W + (size_t)(nb + 3) * 128 + k4 * 4);
                *(float4*)(WtM + (4 * k4 + 0) * 128 + nb) = make_float4(r0.x, r1.x, r2.x, r3.x);
                *(float4*)(WtM + (4 * k4 + 1) * 128 + nb) = make_float4(r0.y, r1.y, r2.y, r3.y);
                *(float4*)(WtM + (4 * k4 + 2) * 128 + nb) = make_float4(r0.z, r1.z, r2.z, r3.z);
                *(float4*)(WtM + (4 * k4 + 3) * 128 + nb) = make_float4(r0.w, r1.w, r2.w, r3.w);
            }
        }
    }

    // acc2[i][j]: rows ty+32i, col-pairs (tx*8 + 2j, tx*8 + 2j + 1)
    ull acc2[4][4];
    #pragma unroll
    for (int i = 0; i < 4; i++)
        #pragma unroll
        for (int j = 0; j < 4; j++) acc2[i][j] = 0ull;

    // Two k-phases: phase 0 = aggregated neighbors (vs Wl),
    //               phase 1 = self features       (vs Wr).
    for (int ph = 0; ph < 2; ph++) {
        __syncthreads();   // prev-phase reads done / weight-stores visible
        {
            const int kq = tid & 31;
            #pragma unroll
            for (int it = 0; it < 8; it++) {
                int rowl = (tid >> 5) + 16 * it;    // 0..127
                int rowg = row0 + rowl;
                float4 v = make_float4(0.f, 0.f, 0.f, 0.f);
                if (rowg < n_nodes) {
                    if (ph == 0) {
                        v = *(const float4*)(sum + (size_t)rowg * DD + kq * 4);
                        float inv = 1.0f / fmaxf(cnt[rowg], 1.0f);
                        v.x *= inv; v.y *= inv; v.z *= inv; v.w *= inv;
                    } else {
                        v = *(const float4*)(x + (size_t)rowg * DD + kq * 4);
                    }
                }
                As4[rowl * 32 + (kq ^ (rowl & 31))] = v;  // XOR swizzle
            }
        }
        __syncthreads();

        const float4* Wt4 = (const float4*)(Wt + ph * 128 * 128);
        #pragma unroll 2
        for (int kq = 0; kq < 32; kq++) {
            // a: 4 k-values per row, one LDS.128 per row
            float4 a4[4];
            #pragma unroll
            for (int i = 0; i < 4; i++) {
                int m = ty + 32 * i;
                a4[i] = As4[m * 32 + (kq ^ (m & 31))];
            }
            #pragma unroll
            for (int kr = 0; kr < 4; kr++) {
                int k = kq * 4 + kr;
                // b pairs straight from smem as aligned 64-bit values (no repack)
                ulonglong2 b0 = *(const ulonglong2*)&Wt4[k * 32 + tx * 2];
                ulonglong2 b1 = *(const ulonglong2*)&Wt4[k * 32 + tx * 2 + 1];
                #pragma unroll
                for (int i = 0; i < 4; i++) {
                    float av = (kr == 0) ? a4[i].x : (kr == 1) ? a4[i].y
                             : (kr == 2) ? a4[i].z : a4[i].w;
                    ull a2 = pack2(av, av);
                    fma2(acc2[i][0], a2, b0.x);
                    fma2(acc2[i][1], a2, b0.y);
                    fma2(acc2[i][2], a2, b1.x);
                    fma2(acc2[i][3], a2, b1.y);
                }
            }
        }
    }

    // Epilogue: bias (+ exact-erf GELU for layer 0), coalesced float4 stores.
    float bv[8];
    #pragma unroll
    for (int j = 0; j < 8; j++) bv[j] = bias[tx * 8 + j];

    #pragma unroll
    for (int i = 0; i < 4; i++) {
        int m = row0 + ty + 32 * i;
        if (m < n_nodes) {
            float o[8];
            #pragma unroll
            for (int j = 0; j < 4; j++) {
                float2 p = unpack2(acc2[i][j]);
                o[2 * j]     = p.x + bv[2 * j];
                o[2 * j + 1] = p.y + bv[2 * j + 1];
            }
            if (do_gelu) {
                #pragma unroll
                for (int j = 0; j < 8; j++)
                    o[j] = 0.5f * o[j] * (1.0f + erff(o[j] * 0.70710678118654752f));
            }
            *(float4*)(out + (size_t)m * DD + tx * 8)     = make_float4(o[0], o[1], o[2], o[3]);
            *(float4*)(out + (size_t)m * DD + tx * 8 + 4) = make_float4(o[4], o[5], o[6], o[7]);
        }
    }
}

// ---------------------------------------------------------------------------
extern "C" void kernel_launch(void* const* d_in, const int* in_sizes, int n_in,
                              void* d_out, int out_size)
{
    const float* embs = (const float*)d_in[0];
    const int*   ei0  = (const int*)d_in[1];
    const int*   ei1  = (const int*)d_in[2];
    const float* wl0  = (const float*)d_in[3];
    const float* wr0  = (const float*)d_in[4];
    const float* b0   = (const float*)d_in[5];
    const float* wl1  = (const float*)d_in[6];
    const float* wr1  = (const float*)d_in[7];
    const float* b1   = (const float*)d_in[8];
    float* out = (float*)d_out;

    const int N  = in_sizes[0] / DD;
    const int E0 = in_sizes[1] / 2;
    const int E1 = in_sizes[2] / 2;

    float *dsum, *dcnt, *dx1;
    cudaGetSymbolAddress((void**)&dsum, g_sum);
    cudaGetSymbolAddress((void**)&dcnt, g_cnt);
    cudaGetSymbolAddress((void**)&dx1,  g_x1);

    const size_t SMEM = (256 * 128 + 128 * 32 * 4) * sizeof(float);  // 192KB
    cudaFuncSetAttribute(fused_kernel,
                         cudaFuncAttributeMaxDynamicSharedMemorySize, (int)SMEM);

    const int gemm_blocks = (N + TM - 1) / TM;

    // ---- layer 0 ----
    cudaMemsetAsync(dsum, 0, (size_t)NN * DD * sizeof(float));
    cudaMemsetAsync(dcnt, 0, (size_t)NN * sizeof(float));
    {
        long long threads = (long long)E0 * 32;
        int blocks = (int)((threads + 255) / 256);
        scatter_kernel<<<blocks, 256>>>(embs, ei0, E0, dsum, dcnt);
    }
    fused_kernel<<<gemm_blocks, 512, SMEM>>>(embs, dsum, dcnt, wl0, wr0, b0,
                                             dx1, N, 1);

    // ---- layer 1 ----
    cudaMemsetAsync(dsum, 0, (size_t)NN * DD * sizeof(float));
    cudaMemsetAsync(dcnt, 0, (size_t)NN * sizeof(float));
    {
        long long threads = (long long)E1 * 32;
        int blocks = (int)((threads + 255) / 256);
        scatter_kernel<<<blocks, 256>>>(dx1, ei1, E1, dsum, dcnt);
    }
    fused_kernel<<<gemm_blocks, 512, SMEM>>>(dx1, dsum, dcnt, wl1, wr1, b1,
                                             out, N, 0);
}

// round 4
// speedup vs baseline: 1.6819x; 1.6819x over previous
#include <cuda_runtime.h>
#include <math.h>

#define NN 100000
#define NE 1600000
#define DD 128

// Scratch (device globals — no allocation allowed)
__device__ __align__(16) float g_agg[(size_t)NN * DD];
__device__ __align__(16) float g_x1[(size_t)NN * DD];
__device__ int g_cnt[NN];
__device__ int g_cur[NN];
__device__ int g_rowptr[NN + 1];
__device__ int g_csr[NE];

// ---------------------------------------------------------------------------
// CSR build: count -> scan -> fill
// ---------------------------------------------------------------------------
__global__ void count_kernel(const int* __restrict__ ei, int E,
                             int* __restrict__ cnt)
{
    int t = blockIdx.x * blockDim.x + threadIdx.x;
    if (t < E) atomicAdd(cnt + ei[E + t], 1);
}

// Single-block exclusive scan over n counts -> rowptr[0..n] (1024 threads).
__global__ void scan_kernel(const int* __restrict__ cnt,
                            int* __restrict__ rowptr, int n)
{
    __shared__ int ssum[1024];
    const int t = threadIdx.x;
    const int chunk = (n + 1023) / 1024;
    int beg = t * chunk;
    int end = min(beg + chunk, n);
    if (beg > n) beg = n;

    int s = 0;
    for (int i = beg; i < end; i++) s += cnt[i];
    ssum[t] = s;
    __syncthreads();
    #pragma unroll
    for (int off = 1; off < 1024; off <<= 1) {
        int v = (t >= off) ? ssum[t - off] : 0;
        __syncthreads();
        ssum[t] += v;
        __syncthreads();
    }
    int base = ssum[t] - s;   // exclusive prefix for this chunk
    for (int i = beg; i < end; i++) { rowptr[i] = base; base += cnt[i]; }
    if (t == 1023) rowptr[n] = ssum[1023];
}

__global__ void fill_kernel(const int* __restrict__ ei, int E,
                            const int* __restrict__ rowptr,
                            int* __restrict__ cur, int* __restrict__ csr)
{
    int t = blockIdx.x * blockDim.x + threadIdx.x;
    if (t < E) {
        int src = ei[t];
        int dst = ei[E + t];
        int pos = atomicAdd(cur + dst, 1);
        csr[rowptr[dst] + pos] = src;
    }
}

// ---------------------------------------------------------------------------
// Gather: one warp per destination node; mean of neighbor rows, no atomics.
// ---------------------------------------------------------------------------
__global__ void gather_kernel(const float* __restrict__ x,
                              const int* __restrict__ rowptr,
                              const int* __restrict__ csr,
                              float* __restrict__ agg, int n)
{
    int w = (blockIdx.x * blockDim.x + threadIdx.x) >> 5;
    if (w >= n) return;
    const int lane = threadIdx.x & 31;
    const int beg = rowptr[w];
    const int end = rowptr[w + 1];

    float4 acc = make_float4(0.f, 0.f, 0.f, 0.f);
    int i = beg;
    for (; i + 4 <= end; i += 4) {               // MLP=4 over L2
        int s0 = __ldg(csr + i);
        int s1 = __ldg(csr + i + 1);
        int s2 = __ldg(csr + i + 2);
        int s3 = __ldg(csr + i + 3);
        float4 v0 = *(const float4*)(x + (size_t)s0 * DD + lane * 4);
        float4 v1 = *(const float4*)(x + (size_t)s1 * DD + lane * 4);
        float4 v2 = *(const float4*)(x + (size_t)s2 * DD + lane * 4);
        float4 v3 = *(const float4*)(x + (size_t)s3 * DD + lane * 4);
        acc.x += v0.x + v1.x + v2.x + v3.x;
        acc.y += v0.y + v1.y + v2.y + v3.y;
        acc.z += v0.z + v1.z + v2.z + v3.z;
        acc.w += v0.w + v1.w + v2.w + v3.w;
    }
    for (; i < end; i++) {
        int s = __ldg(csr + i);
        float4 v = *(const float4*)(x + (size_t)s * DD + lane * 4);
        acc.x += v.x; acc.y += v.y; acc.z += v.z; acc.w += v.w;
    }
    float inv = 1.0f / fmaxf((float)(end - beg), 1.0f);
    acc.x *= inv; acc.y *= inv; acc.z *= inv; acc.w *= inv;
    *(float4*)(agg + (size_t)w * DD + lane * 4) = acc;
}

// ---------------------------------------------------------------------------
// Fused per-layer GEMM: out[i,:] = act( agg[i,:] @ Wl^T + x[i,:] @ Wr^T + b )
// Tile 64 rows x 128 cols, 256 threads, 4x8 microtile. Per-phase weight
// reload keeps smem at 96KB -> 2 CTAs/SM for latency hiding.
// ---------------------------------------------------------------------------
__global__ void __launch_bounds__(256, 2) fused_kernel(
    const float* __restrict__ x,
    const float* __restrict__ agg,
    const float* __restrict__ wl,
    const float* __restrict__ wr,
    const float* __restrict__ bias,
    float* __restrict__ out,
    int n_nodes, int do_gelu)
{
    extern __shared__ float smem[];
    float*  Wt  = smem;                         // 128*128 floats = 64KB
    float4* As4 = (float4*)(smem + 128 * 128);  // 64*32 float4  = 32KB (swizzled)

    const int tid = threadIdx.x;
    const int tx = tid & 15;      // n: 8 cols each
    const int ty = tid >> 4;      // m: rows ty + 16*i, i<4
    const int row0 = blockIdx.x * 64;

    float acc[4][8];
    #pragma unroll
    for (int i = 0; i < 4; i++)
        #pragma unroll
        for (int j = 0; j < 8; j++) acc[i][j] = 0.0f;

    // Two k-phases: 0 = agg vs Wl, 1 = x vs Wr.
    for (int ph = 0; ph < 2; ph++) {
        __syncthreads();   // prior-phase smem reads complete

        // Weight transpose into smem: Wt[k][n] = W[n][k]
        {
            const float* W = ph ? wr : wl;
            const int nb = (tid & 31) * 4;   // n block of 4
            const int kb = tid >> 5;         // 0..7
            #pragma unroll
            for (int it = 0; it < 4; it++) {
                int k4 = kb + 8 * it;        // float4 chunk along k
                float4 r0 = *(const float4*)(W + (size_t)(nb + 0) * 128 + k4 * 4);
                float4 r1 = *(const float4*)(W + (size_t)(nb + 1) * 128 + k4 * 4);
                float4 r2 = *(const float4*)(W + (size_t)(nb + 2) * 128 + k4 * 4);
                float4 r3 = *(const float4*)(W + (size_t)(nb + 3) * 128 + k4 * 4);
                *(float4*)(Wt + (4 * k4 + 0) * 128 + nb) = make_float4(r0.x, r1.x, r2.x, r3.x);
                *(float4*)(Wt + (4 * k4 + 1) * 128 + nb) = make_float4(r0.y, r1.y, r2.y, r3.y);
                *(float4*)(Wt + (4 * k4 + 2) * 128 + nb) = make_float4(r0.z, r1.z, r2.z, r3.z);
                *(float4*)(Wt + (4 * k4 + 3) * 128 + nb) = make_float4(r0.w, r1.w, r2.w, r3.w);
            }
        }
        // A tile (64 rows x 128), XOR-swizzled float4
        {
            const float* A = ph ? x : agg;
            const int kq = tid & 31;
            #pragma unroll
            for (int it = 0; it < 8; it++) {
                int rowl = (tid >> 5) + 8 * it;     // 0..63
                int rowg = row0 + rowl;
                float4 v = make_float4(0.f, 0.f, 0.f, 0.f);
                if (rowg < n_nodes)
                    v = *(const float4*)(A + (size_t)rowg * DD + kq * 4);
                As4[rowl * 32 + (kq ^ (rowl & 31))] = v;
            }
        }
        __syncthreads();

        const float4* Wt4 = (const float4*)Wt;
        #pragma unroll 2
        for (int kq = 0; kq < 32; kq++) {
            float4 a4[4];
            #pragma unroll
            for (int i = 0; i < 4; i++) {
                int m = ty + 16 * i;
                a4[i] = As4[m * 32 + (kq ^ (m & 31))];
            }
            #pragma unroll
            for (int kr = 0; kr < 4; kr++) {
                int k = kq * 4 + kr;
                float4 b0 = Wt4[k * 32 + tx * 2];
                float4 b1 = Wt4[k * 32 + tx * 2 + 1];
                #pragma unroll
                for (int i = 0; i < 4; i++) {
                    float av = (kr == 0) ? a4[i].x : (kr == 1) ? a4[i].y
                             : (kr == 2) ? a4[i].z : a4[i].w;
                    acc[i][0] += av * b0.x;
                    acc[i][1] += av * b0.y;
                    acc[i][2] += av * b0.z;
                    acc[i][3] += av * b0.w;
                    acc[i][4] += av * b1.x;
                    acc[i][5] += av * b1.y;
                    acc[i][6] += av * b1.z;
                    acc[i][7] += av * b1.w;
                }
            }
        }
    }

    // Epilogue: bias (+ exact-erf GELU for layer 0), coalesced float4 stores.
    float bv[8];
    #pragma unroll
    for (int j = 0; j < 8; j++) bv[j] = bias[tx * 8 + j];

    #pragma unroll
    for (int i = 0; i < 4; i++) {
        int m = row0 + ty + 16 * i;
        if (m < n_nodes) {
            float o[8];
            #pragma unroll
            for (int j = 0; j < 8; j++) {
                float v = acc[i][j] + bv[j];
                if (do_gelu) v = 0.5f * v * (1.0f + erff(v * 0.70710678118654752f));
                o[j] = v;
            }
            *(float4*)(out + (size_t)m * DD + tx * 8)     = make_float4(o[0], o[1], o[2], o[3]);
            *(float4*)(out + (size_t)m * DD + tx * 8 + 4) = make_float4(o[4], o[5], o[6], o[7]);
        }
    }
}

// ---------------------------------------------------------------------------
extern "C" void kernel_launch(void* const* d_in, const int* in_sizes, int n_in,
                              void* d_out, int out_size)
{
    const float* embs = (const float*)d_in[0];
    const int*   ei0  = (const int*)d_in[1];
    const int*   ei1  = (const int*)d_in[2];
    const float* wl0  = (const float*)d_in[3];
    const float* wr0  = (const float*)d_in[4];
    const float* b0   = (const float*)d_in[5];
    const float* wl1  = (const float*)d_in[6];
    const float* wr1  = (const float*)d_in[7];
    const float* b1   = (const float*)d_in[8];
    float* out = (float*)d_out;

    const int N  = in_sizes[0] / DD;
    const int E0 = in_sizes[1] / 2;
    const int E1 = in_sizes[2] / 2;

    float *dagg, *dx1;
    int *dcnt, *dcur, *drp, *dcsr;
    cudaGetSymbolAddress((void**)&dagg, g_agg);
    cudaGetSymbolAddress((void**)&dx1,  g_x1);
    cudaGetSymbolAddress((void**)&dcnt, g_cnt);
    cudaGetSymbolAddress((void**)&dcur, g_cur);
    cudaGetSymbolAddress((void**)&drp,  g_rowptr);
    cudaGetSymbolAddress((void**)&dcsr, g_csr);

    const size_t SMEM = (128 * 128 + 64 * 32 * 4) * sizeof(float);  // 96KB
    cudaFuncSetAttribute(fused_kernel,
                         cudaFuncAttributeMaxDynamicSharedMemorySize, (int)SMEM);

    const int gemm_blocks = (N + 63) / 64;
    const int gather_blocks = (N * 32 + 255) / 256;

    // ---- layer 0 ----
    cudaMemsetAsync(dcnt, 0, NN * sizeof(int));
    cudaMemsetAsync(dcur, 0, NN * sizeof(int));
    count_kernel<<<(E0 + 255) / 256, 256>>>(ei0, E0, dcnt);
    scan_kernel<<<1, 1024>>>(dcnt, drp, N);
    fill_kernel<<<(E0 + 255) / 256, 256>>>(ei0, E0, drp, dcur, dcsr);
    gather_kernel<<<gather_blocks, 256>>>(embs, drp, dcsr, dagg, N);
    fused_kernel<<<gemm_blocks, 256, SMEM>>>(embs, dagg, wl0, wr0, b0,
                                             dx1, N, 1);

    // ---- layer 1 ----
    cudaMemsetAsync(dcnt, 0, NN * sizeof(int));
    cudaMemsetAsync(dcur, 0, NN * sizeof(int));
    count_kernel<<<(E1 + 255) / 256, 256>>>(ei1, E1, dcnt);
    scan_kernel<<<1, 1024>>>(dcnt, drp, N);
    fill_kernel<<<(E1 + 255) / 256, 256>>>(ei1, E1, drp, dcur, dcsr);
    gather_kernel<<<gather_blocks, 256>>>(dx1, drp, dcsr, dagg, N);
    fused_kernel<<<gemm_blocks, 256, SMEM>>>(dx1, dagg, wl1, wr1, b1,
                                             out, N, 0);
}

// round 7
// speedup vs baseline: 1.8435x; 1.0960x over previous
#include <cuda_runtime.h>
#include <math.h>

#define NN 100000
#define NE 1600000
#define DD 128
#define TM 256

// Scratch (device globals — no allocation allowed)
__device__ __align__(16) float g_agg[(size_t)NN * DD];
__device__ __align__(16) float g_x1[(size_t)NN * DD];
__device__ int g_cnt[NN];
__device__ int g_rp2[NN];          // mutable copy of rowptr for fill
__device__ int g_rowptr[NN + 1];
__device__ int g_csr[NE];

// ---------------------------------------------------------------------------
// CSR build: count -> scan (writes rowptr + rp2) -> fill
// ---------------------------------------------------------------------------
__global__ void count_kernel(const int* __restrict__ ei, int E,
                             int* __restrict__ cnt)
{
    int t = blockIdx.x * blockDim.x + threadIdx.x;
    if (t < E) atomicAdd(cnt + ei[E + t], 1);
}

// Single-block exclusive scan over n counts -> rowptr[0..n], rp2[0..n-1].
__global__ void scan_kernel(const int* __restrict__ cnt,
                            int* __restrict__ rowptr,
                            int* __restrict__ rp2, int n)
{
    __shared__ int ssum[1024];
    const int t = threadIdx.x;
    const int chunk = (n + 1023) / 1024;
    int beg = t * chunk;
    int end = min(beg + chunk, n);
    if (beg > n) beg = n;

    int s = 0;
    for (int i = beg; i < end; i++) s += cnt[i];
    ssum[t] = s;
    __syncthreads();
    #pragma unroll
    for (int off = 1; off < 1024; off <<= 1) {
        int v = (t >= off) ? ssum[t - off] : 0;
        __syncthreads();
        ssum[t] += v;
        __syncthreads();
    }
    int base = ssum[t] - s;   // exclusive prefix for this chunk
    for (int i = beg; i < end; i++) {
        rowptr[i] = base;
        rp2[i] = base;
        base += cnt[i];
    }
    if (t == 1023) rowptr[n] = ssum[1023];
}

__global__ void fill_kernel(const int* __restrict__ ei, int E,
                            int* __restrict__ rp2, int* __restrict__ csr)
{
    int t = blockIdx.x * blockDim.x + threadIdx.x;
    if (t < E) {
        int src = ei[t];
        int dst = ei[E + t];
        int pos = atomicAdd(rp2 + dst, 1);   // absolute slot
        csr[pos] = src;
    }
}

// ---------------------------------------------------------------------------
// Gather: one warp per destination node; mean of neighbor rows, no atomics.
// ---------------------------------------------------------------------------
__global__ void gather_kernel(const float* __restrict__ x,
                              const int* __restrict__ rowptr,
                              const int* __restrict__ csr,
                              float* __restrict__ agg, int n)
{
    int w = (blockIdx.x * blockDim.x + threadIdx.x) >> 5;
    if (w >= n) return;
    const int lane = threadIdx.x & 31;
    const int beg = rowptr[w];
    const int end = rowptr[w + 1];

    float4 acc = make_float4(0.f, 0.f, 0.f, 0.f);
    int i = beg;
    for (; i + 4 <= end; i += 4) {               // MLP=4 over L2
        int s0 = __ldg(csr + i);
        int s1 = __ldg(csr + i + 1);
        int s2 = __ldg(csr + i + 2);
        int s3 = __ldg(csr + i + 3);
        float4 v0 = *(const float4*)(x + (size_t)s0 * DD + lane * 4);
        float4 v1 = *(const float4*)(x + (size_t)s1 * DD + lane * 4);
        float4 v2 = *(const float4*)(x + (size_t)s2 * DD + lane * 4);
        float4 v3 = *(const float4*)(x + (size_t)s3 * DD + lane * 4);
        acc.x += v0.x + v1.x + v2.x + v3.x;
        acc.y += v0.y + v1.y + v2.y + v3.y;
        acc.z += v0.z + v1.z + v2.z + v3.z;
        acc.w += v0.w + v1.w + v2.w + v3.w;
    }
    for (; i < end; i++) {
        int s = __ldg(csr + i);
        float4 v = *(const float4*)(x + (size_t)s * DD + lane * 4);
        acc.x += v.x; acc.y += v.y; acc.z += v.z; acc.w += v.w;
    }
    float inv = 1.0f / fmaxf((float)(end - beg), 1.0f);
    acc.x *= inv; acc.y *= inv; acc.z *= inv; acc.w *= inv;
    *(float4*)(agg + (size_t)w * DD + lane * 4) = acc;
}

// ---------------------------------------------------------------------------
// Fused per-layer GEMM: out[i,:] = act( agg[i,:] @ Wl^T + x[i,:] @ Wr^T + b )
// Tile 256 rows x 128 cols, 512 threads, 8x8 microtile (16 warps = 4/SMSP,
// FFMA:LDS = 16). smem: Wt[128][128] per phase (64KB) + swizzled A (128KB).
// ---------------------------------------------------------------------------
__global__ void __launch_bounds__(512, 1) fused_kernel(
    const float* __restrict__ x,
    const float* __restrict__ agg,
    const float* __restrict__ wl,
    const float* __restrict__ wr,
    const float* __restrict__ bias,
    float* __restrict__ out,
    int n_nodes, int do_gelu)
{
    extern __shared__ float smem[];
    float*  Wt  = smem;                         // 128*128 floats = 64KB
    float4* As4 = (float4*)(smem + 128 * 128);  // 256*32 float4 = 128KB (swizzled)

    const int tid = threadIdx.x;
    const int tx = tid & 15;      // n: cols tx*8 .. tx*8+7
    const int ty = tid >> 4;      // m: rows ty + 32*i, i<8
    const int row0 = blockIdx.x * TM;

    float acc[8][8];
    #pragma unroll
    for (int i = 0; i < 8; i++)
        #pragma unroll
        for (int j = 0; j < 8; j++) acc[i][j] = 0.0f;

    // Two k-phases: 0 = agg vs Wl, 1 = x vs Wr.
    for (int ph = 0; ph < 2; ph++) {
        __syncthreads();   // prior-phase smem reads complete

        // Weight transpose into smem: Wt[k][n] = W[n][k]
        {
            const float* W = ph ? wr : wl;
            const int nb = (tid & 31) * 4;   // n block of 4
            const int kb = tid >> 5;         // 0..15
            #pragma unroll
            for (int it = 0; it < 2; it++) {
                int k4 = kb + 16 * it;       // float4 chunk along k: 0..31
                float4 r0 = *(const float4*)(W + (size_t)(nb + 0) * 128 + k4 * 4);
                float4 r1 = *(const float4*)(W + (size_t)(nb + 1) * 128 + k4 * 4);
                float4 r2 = *(const float4*)(W + (size_t)(nb + 2) * 128 + k4 * 4);
                float4 r3 = *(const float4*)(W + (size_t)(nb + 3) * 128 + k4 * 4);
                *(float4*)(Wt + (4 * k4 + 0) * 128 + nb) = make_float4(r0.x, r1.x, r2.x, r3.x);
                *(float4*)(Wt + (4 * k4 + 1) * 128 + nb) = make_float4(r0.y, r1.y, r2.y, r3.y);
                *(float4*)(Wt + (4 * k4 + 2) * 128 + nb) = make_float4(r0.z, r1.z, r2.z, r3.z);
                *(float4*)(Wt + (4 * k4 + 3) * 128 + nb) = make_float4(r0.w, r1.w, r2.w, r3.w);
            }
        }
        // A tile (256 rows x 128), XOR-swizzled float4
        {
            const float* A = ph ? x : agg;
            const int kq = tid & 31;
            #pragma unroll
            for (int it = 0; it < 16; it++) {
                int rowl = (tid >> 5) + 16 * it;     // 0..255
                int rowg = row0 + rowl;
                float4 v = make_float4(0.f, 0.f, 0.f, 0.f);
                if (rowg < n_nodes)
                    v = *(const float4*)(A + (size_t)rowg * DD + kq * 4);
                As4[rowl * 32 + (kq ^ (rowl & 31))] = v;
            }
        }
        __syncthreads();

        const float4* Wt4 = (const float4*)Wt;
        #pragma unroll 2
        for (int kq = 0; kq < 32; kq++) {
            // one LDS.128 per row; m&31 == ty for all i (swizzle idx constant)
            float4 a4[8];
            #pragma unroll
            for (int i = 0; i < 8; i++) {
                int m = ty + 32 * i;
                a4[i] = As4[m * 32 + (kq ^ ty)];
            }
            #pragma unroll
            for (int kr = 0; kr < 4; kr++) {
                int k = kq * 4 + kr;
                float4 b0 = Wt4[k * 32 + tx * 2];
                float4 b1 = Wt4[k * 32 + tx * 2 + 1];
                #pragma unroll
                for (int i = 0; i < 8; i++) {
                    float av = (kr == 0) ? a4[i].x : (kr == 1) ? a4[i].y
                             : (kr == 2) ? a4[i].z : a4[i].w;
                    acc[i][0] += av * b0.x;
                    acc[i][1] += av * b0.y;
                    acc[i][2] += av * b0.z;
                    acc[i][3] += av * b0.w;
                    acc[i][4] += av * b1.x;
                    acc[i][5] += av * b1.y;
                    acc[i][6] += av * b1.z;
                    acc[i][7] += av * b1.w;
                }
            }
        }
    }

    // Epilogue: bias (+ exact-erf GELU for layer 0), coalesced float4 stores.
    float bv[8];
    #pragma unroll
    for (int j = 0; j < 8; j++) bv[j] = bias[tx * 8 + j];

    #pragma unroll
    for (int i = 0; i < 8; i++) {
        int m = row0 + ty + 32 * i;
        if (m < n_nodes) {
            float o[8];
            #pragma unroll
            for (int j = 0; j < 8; j++) {
                float v = acc[i][j] + bv[j];
                if (do_gelu) v = 0.5f * v * (1.0f + erff(v * 0.70710678118654752f));
                o[j] = v;
            }
            *(float4*)(out + (size_t)m * DD + tx * 8)     = make_float4(o[0], o[1], o[2], o[3]);
            *(float4*)(out + (size_t)m * DD + tx * 8 + 4) = make_float4(o[4], o[5], o[6], o[7]);
        }
    }
}

// ---------------------------------------------------------------------------
extern "C" void kernel_launch(void* const* d_in, const int* in_sizes, int n_in,
                              void* d_out, int out_size)
{
    const float* embs = (const float*)d_in[0];
    const int*   ei0  = (const int*)d_in[1];
    const int*   ei1  = (const int*)d_in[2];
    const float* wl0  = (const float*)d_in[3];
    const float* wr0  = (const float*)d_in[4];
    const float* b0   = (const float*)d_in[5];
    const float* wl1  = (const float*)d_in[6];
    const float* wr1  = (const float*)d_in[7];
    const float* b1   = (const float*)d_in[8];
    float* out = (float*)d_out;

    const int N  = in_sizes[0] / DD;
    const int E0 = in_sizes[1] / 2;
    const int E1 = in_sizes[2] / 2;

    float *dagg, *dx1;
    int *dcnt, *drp2, *drp, *dcsr;
    cudaGetSymbolAddress((void**)&dagg, g_agg);
    cudaGetSymbolAddress((void**)&dx1,  g_x1);
    cudaGetSymbolAddress((void**)&dcnt, g_cnt);
    cudaGetSymbolAddress((void**)&drp2, g_rp2);
    cudaGetSymbolAddress((void**)&drp,  g_rowptr);
    cudaGetSymbolAddress((void**)&dcsr, g_csr);

    const size_t SMEM = (128 * 128 + TM * 32 * 4) * sizeof(float);  // 192KB
    cudaFuncSetAttribute(fused_kernel,
                         cudaFuncAttributeMaxDynamicSharedMemorySize, (int)SMEM);

    const int gemm_blocks = (N + TM - 1) / TM;
    const int gather_blocks = (N * 32 + 255) / 256;

    // ---- layer 0 ----
    cudaMemsetAsync(dcnt, 0, NN * sizeof(int));
    count_kernel<<<(E0 + 255) / 256, 256>>>(ei0, E0, dcnt);
    scan_kernel<<<1, 1024>>>(dcnt, drp, drp2, N);
    fill_kernel<<<(E0 + 255) / 256, 256>>>(ei0, E0, drp2, dcsr);
    gather_kernel<<<gather_blocks, 256>>>(embs, drp, dcsr, dagg, N);
    fused_kernel<<<gemm_blocks, 512, SMEM>>>(embs, dagg, wl0, wr0, b0,
                                             dx1, N, 1);

    // ---- layer 1 ----
    cudaMemsetAsync(dcnt, 0, NN * sizeof(int));
    count_kernel<<<(E1 + 255) / 256, 256>>>(ei1, E1, dcnt);
    scan_kernel<<<1, 1024>>>(dcnt, drp, drp2, N);
    fill_kernel<<<(E1 + 255) / 256, 256>>>(ei1, E1, drp2, dcsr);
    gather_kernel<<<gather_blocks, 256>>>(dx1, drp, dcsr, dagg, N);
    fused_kernel<<<gemm_blocks, 512, SMEM>>>(dx1, dagg, wl1, wr1, b1,
                                             out, N, 0);
}

// round 8
// speedup vs baseline: 2.7001x; 1.4647x over previous
#include <cuda_runtime.h>
#include <cuda_bf16.h>
#include <math.h>

#define NN 100000
#define NE 1600000
#define DD 128

// Scratch (device globals — no allocation allowed)
__device__ __align__(16) float g_agg[(size_t)NN * DD];
__device__ __align__(16) float g_x1[(size_t)NN * DD];
__device__ int g_cnt[2 * NN];
__device__ int g_rp2[2 * NN];
__device__ int g_rowptr[2 * (NN + 1)];
__device__ int g_csr[2 * NE];

// ---------------------------------------------------------------------------
// smem geometry for fused_tc: bf16 tiles padded to 136 elems (272B) per row.
// ---------------------------------------------------------------------------
#define SA 136
#define TILEB (128 * SA * 2)            // 34816 B per tile
#define OFF_AHI 0
#define OFF_ALO (OFF_AHI + TILEB)
#define OFF_BHI (OFF_ALO + TILEB)
#define OFF_BLO (OFF_BHI + TILEB)
#define OFF_BIAS (OFF_BLO + TILEB)
#define SM_TOTAL (OFF_BIAS + 512)       // ~140 KB

__device__ __forceinline__ unsigned smem_u32(const void* p) {
    unsigned a;
    asm("{ .reg .u64 t; cvta.to.shared.u64 t, %1; cvt.u32.u64 %0, t; }"
        : "=r"(a) : "l"(p));
    return a;
}
__device__ __forceinline__ void ldsm4(unsigned* d, unsigned addr) {
    asm volatile("ldmatrix.sync.aligned.m8n8.x4.shared.b16 {%0,%1,%2,%3}, [%4];"
                 : "=r"(d[0]), "=r"(d[1]), "=r"(d[2]), "=r"(d[3]) : "r"(addr));
}
__device__ __forceinline__ void mma16816(float* c, const unsigned* a,
                                         const unsigned* b) {
    asm volatile("mma.sync.aligned.m16n8k16.row.col.f32.bf16.bf16.f32 "
                 "{%0,%1,%2,%3}, {%4,%5,%6,%7}, {%8,%9}, {%0,%1,%2,%3};"
                 : "+f"(c[0]), "+f"(c[1]), "+f"(c[2]), "+f"(c[3])
                 : "r"(a[0]), "r"(a[1]), "r"(a[2]), "r"(a[3]),
                   "r"(b[0]), "r"(b[1]));
}

// ---------------------------------------------------------------------------
// CSR build for BOTH layers: count -> scan (2 blocks) -> fill
// ---------------------------------------------------------------------------
__global__ void count_both(const int* __restrict__ ei0, const int* __restrict__ ei1,
                           int E0, int E1, int* __restrict__ cnt)
{
    int t = blockIdx.x * blockDim.x + threadIdx.x;
    if (t < E0) atomicAdd(cnt + ei0[E0 + t], 1);
    else if (t < E0 + E1) atomicAdd(cnt + NN + ei1[E1 + (t - E0)], 1);
}

__global__ void scan_both(const int* __restrict__ cnt_all,
                          int* __restrict__ rowptr_all,
                          int* __restrict__ rp2_all, int n)
{
    __shared__ int ssum[1024];
    const int L = blockIdx.x;
    const int* cnt = cnt_all + L * NN;
    int* rowptr = rowptr_all + L * (NN + 1);
    int* rp2 = rp2_all + L * NN;

    const int t = threadIdx.x;
    const int chunk = (n + 1023) / 1024;
    int beg = t * chunk;
    int end = min(beg + chunk, n);
    if (beg > n) beg = n;

    int s = 0;
    for (int i = beg; i < end; i++) s += cnt[i];
    ssum[t] = s;
    __syncthreads();
    #pragma unroll
    for (int off = 1; off < 1024; off <<= 1) {
        int v = (t >= off) ? ssum[t - off] : 0;
        __syncthreads();
        ssum[t] += v;
        __syncthreads();
    }
    int base = ssum[t] - s;
    for (int i = beg; i < end; i++) {
        rowptr[i] = base;
        rp2[i] = base;
        base += cnt[i];
    }
    if (t == 1023) rowptr[n] = ssum[1023];
}

__global__ void fill_both(const int* __restrict__ ei0, const int* __restrict__ ei1,
                          int E0, int E1, int* __restrict__ rp2,
                          int* __restrict__ csr)
{
    int t = blockIdx.x * blockDim.x + threadIdx.x;
    if (t < E0) {
        int src = ei0[t];
        int dst = ei0[E0 + t];
        int pos = atomicAdd(rp2 + dst, 1);
        csr[pos] = src;
    } else if (t < E0 + E1) {
        t -= E0;
        int src = ei1[t];
        int dst = ei1[E1 + t];
        int pos = atomicAdd(rp2 + NN + dst, 1);
        csr[NE + pos] = src;
    }
}

// ---------------------------------------------------------------------------
// Gather: one warp per destination node; mean of neighbor rows, no atomics.
// ---------------------------------------------------------------------------
__global__ void gather_kernel(const float* __restrict__ x,
                              const int* __restrict__ rowptr,
                              const int* __restrict__ csr,
                              float* __restrict__ agg, int n)
{
    int w = (blockIdx.x * blockDim.x + threadIdx.x) >> 5;
    if (w >= n) return;
    const int lane = threadIdx.x & 31;
    const int beg = rowptr[w];
    const int end = rowptr[w + 1];

    float4 acc = make_float4(0.f, 0.f, 0.f, 0.f);
    int i = beg;
    for (; i + 4 <= end; i += 4) {
        int s0 = __ldg(csr + i);
        int s1 = __ldg(csr + i + 1);
        int s2 = __ldg(csr + i + 2);
        int s3 = __ldg(csr + i + 3);
        float4 v0 = *(const float4*)(x + (size_t)s0 * DD + lane * 4);
        float4 v1 = *(const float4*)(x + (size_t)s1 * DD + lane * 4);
        float4 v2 = *(const float4*)(x + (size_t)s2 * DD + lane * 4);
        float4 v3 = *(const float4*)(x + (size_t)s3 * DD + lane * 4);
        acc.x += v0.x + v1.x + v2.x + v3.x;
        acc.y += v0.y + v1.y + v2.y + v3.y;
        acc.z += v0.z + v1.z + v2.z + v3.z;
        acc.w += v0.w + v1.w + v2.w + v3.w;
    }
    for (; i < end; i++) {
        int s = __ldg(csr + i);
        float4 v = *(const float4*)(x + (size_t)s * DD + lane * 4);
        acc.x += v.x; acc.y += v.y; acc.z += v.z; acc.w += v.w;
    }
    float inv = 1.0f / fmaxf((float)(end - beg), 1.0f);
    acc.x *= inv; acc.y *= inv; acc.z *= inv; acc.w *= inv;
    *(float4*)(agg + (size_t)w * DD + lane * 4) = acc;
}

// ---------------------------------------------------------------------------
// Convert 128x128 fp32 (row-guarded) into bf16 hi/lo tiles in smem
// (row stride SA bf16 = 272B). 256 threads: row = tid>>1, col half = (tid&1)*64.
// ---------------------------------------------------------------------------
__device__ __forceinline__ void conv_tile(const float* __restrict__ src,
                                          int row0, int nvalid, char* sm,
                                          int off_hi, int off_lo, int tid)
{
    const int row = tid >> 1;
    const int c0 = (tid & 1) * 64;
    const bool valid = (row0 + row) < nvalid;
    const float* p = src + (size_t)(row0 + row) * DD + c0;
    char* ph = sm + off_hi + (row * SA + c0) * 2;
    char* pl = sm + off_lo + (row * SA + c0) * 2;
    #pragma unroll
    for (int c = 0; c < 64; c += 8) {
        float4 f0 = make_float4(0.f, 0.f, 0.f, 0.f);
        float4 f1 = make_float4(0.f, 0.f, 0.f, 0.f);
        if (valid) {
            f0 = *(const float4*)(p + c);
            f1 = *(const float4*)(p + c + 4);
        }
        float xs[8] = {f0.x, f0.y, f0.z, f0.w, f1.x, f1.y, f1.z, f1.w};
        unsigned hw[4], lw[4];
        #pragma unroll
        for (int j = 0; j < 4; j++) {
            __nv_bfloat162 h2 = __floats2bfloat162_rn(xs[2 * j], xs[2 * j + 1]);
            float2 hf = __bfloat1622float2(h2);
            __nv_bfloat162 l2 = __floats2bfloat162_rn(xs[2 * j] - hf.x,
                                                      xs[2 * j + 1] - hf.y);
            hw[j] = *(unsigned*)&h2;
            lw[j] = *(unsigned*)&l2;
        }
        *(uint4*)(ph + c * 2) = make_uint4(hw[0], hw[1], hw[2], hw[3]);
        *(uint4*)(pl + c * 2) = make_uint4(lw[0], lw[1], lw[2], lw[3]);
    }
}

// ---------------------------------------------------------------------------
// Fused GEMM on tensor cores (mma.sync bf16, hi/lo split, fp32 accum):
// out[i,:] = act( agg[i,:] @ Wl^T + x[i,:] @ Wr^T + b )
// 128x128 tile per CTA, 256 threads = 8 warps (4 m-warps x 2 n-warps),
// warp tile 32x64. 3 products per phase: Ahi*Bhi + Ahi*Blo + Alo*Bhi.
// ---------------------------------------------------------------------------
__global__ void __launch_bounds__(256, 1) fused_tc(
    const float* __restrict__ x,
    const float* __restrict__ agg,
    const float* __restrict__ wl,
    const float* __restrict__ wr,
    const float* __restrict__ bias,
    float* __restrict__ out,
    int n_nodes, int do_gelu)
{
    extern __shared__ char sm[];
    const int tid = threadIdx.x;
    const int wid = tid >> 5;
    const int lane = tid & 31;
    const int row0 = blockIdx.x * 128;
    const int wm = (wid & 3) * 32;      // warp row base
    const int wn = (wid >> 2) * 64;     // warp col base
    float* sbias = (float*)(sm + OFF_BIAS);

    if (tid < 128) sbias[tid] = bias[tid];

    float acc[2][8][4];
    #pragma unroll
    for (int mt = 0; mt < 2; mt++)
        #pragma unroll
        for (int nt = 0; nt < 8; nt++)
            #pragma unroll
            for (int c = 0; c < 4; c++) acc[mt][nt][c] = 0.0f;

    const unsigned sbase = smem_u32(sm);
    const int lr = lane & 7;
    const int mat = lane >> 3;
    // ldmatrix lane-address components
    const unsigned a_row = wm + lr + ((mat & 1) << 3);
    const unsigned a_co  = ((mat >> 1) << 3);
    const unsigned b_row = wn + lr + ((mat >> 1) << 3);
    const unsigned b_co  = ((mat & 1) << 3);
    const unsigned a_base = sbase + (a_row * SA + a_co) * 2;
    const unsigned b_base = sbase + (b_row * SA + b_co) * 2;

    #pragma unroll 1
    for (int ph = 0; ph < 2; ph++) {
        __syncthreads();   // prior-phase smem reads complete
        conv_tile(ph ? x : agg, row0, n_nodes, sm, OFF_AHI, OFF_ALO, tid);
        conv_tile(ph ? wr : wl, 0, 1 << 30, sm, OFF_BHI, OFF_BLO, tid);
        __syncthreads();

        #pragma unroll 1
        for (int ks = 0; ks < 8; ks++) {
            const unsigned kb = ks * 32;   // 16 bf16 = 32 bytes
            unsigned ahi[2][4], alo[2][4];
            #pragma unroll
            for (int mt = 0; mt < 2; mt++) {
                unsigned off = mt * (16 * SA * 2) + kb;
                ldsm4(ahi[mt], a_base + OFF_AHI + off);
                ldsm4(alo[mt], a_base + OFF_ALO + off);
            }
            unsigned bhi[4][4], blo[4][4];
            #pragma unroll
            for (int np = 0; np < 4; np++) {
                unsigned off = np * (16 * SA * 2) + kb;
                ldsm4(bhi[np], b_base + OFF_BHI + off);
                ldsm4(blo[np], b_base + OFF_BLO + off);
            }
            #pragma unroll
            for (int mt = 0; mt < 2; mt++)
                #pragma unroll
                for (int nt = 0; nt < 8; nt++) {
                    const unsigned* bh = &bhi[nt >> 1][(nt & 1) * 2];
                    const unsigned* bl = &blo[nt >> 1][(nt & 1) * 2];
                    mma16816(acc[mt][nt], ahi[mt], bh);
                    mma16816(acc[mt][nt], ahi[mt], bl);
                    mma16816(acc[mt][nt], alo[mt], bh);
                }
        }
    }

    // Epilogue: c frag (r = lane>>2, c = 2*(lane&3)): {c0,c1}@r, {c2,c3}@r+8
    const int cr = lane >> 2;
    const int cc = 2 * (lane & 3);
    #pragma unroll
    for (int mt = 0; mt < 2; mt++) {
        int r_lo = row0 + wm + mt * 16 + cr;
        int r_hi = r_lo + 8;
        #pragma unroll
        for (int nt = 0; nt < 8; nt++) {
            int col = wn + nt * 8 + cc;
            float b0 = sbias[col], b1 = sbias[col + 1];
            float v0 = acc[mt][nt][0] + b0;
            float v1 = acc[mt][nt][1] + b1;
            float v2 = acc[mt][nt][2] + b0;
            float v3 = acc[mt][nt][3] + b1;
            if (do_gelu) {
                v0 = 0.5f * v0 * (1.0f + erff(v0 * 0.70710678118654752f));
                v1 = 0.5f * v1 * (1.0f + erff(v1 * 0.70710678118654752f));
                v2 = 0.5f * v2 * (1.0f + erff(v2 * 0.70710678118654752f));
                v3 = 0.5f * v3 * (1.0f + erff(v3 * 0.70710678118654752f));
            }
            if (r_lo < n_nodes)
                *(float2*)(out + (size_t)r_lo * DD + col) = make_float2(v0, v1);
            if (r_hi < n_nodes)
                *(float2*)(out + (size_t)r_hi * DD + col) = make_float2(v2, v3);
        }
    }
}

// ---------------------------------------------------------------------------
extern "C" void kernel_launch(void* const* d_in, const int* in_sizes, int n_in,
                              void* d_out, int out_size)
{
    const float* embs = (const float*)d_in[0];
    const int*   ei0  = (const int*)d_in[1];
    const int*   ei1  = (const int*)d_in[2];
    const float* wl0  = (const float*)d_in[3];
    const float* wr0  = (const float*)d_in[4];
    const float* b0   = (const float*)d_in[5];
    const float* wl1  = (const float*)d_in[6];
    const float* wr1  = (const float*)d_in[7];
    const float* b1   = (const float*)d_in[8];
    float* out = (float*)d_out;

    const int N  = in_sizes[0] / DD;
    const int E0 = in_sizes[1] / 2;
    const int E1 = in_sizes[2] / 2;

    float *dagg, *dx1;
    int *dcnt, *drp2, *drp, *dcsr;
    cudaGetSymbolAddress((void**)&dagg, g_agg);
    cudaGetSymbolAddress((void**)&dx1,  g_x1);
    cudaGetSymbolAddress((void**)&dcnt, g_cnt);
    cudaGetSymbolAddress((void**)&drp2, g_rp2);
    cudaGetSymbolAddress((void**)&drp,  g_rowptr);
    cudaGetSymbolAddress((void**)&dcsr, g_csr);

    cudaFuncSetAttribute(fused_tc,
                         cudaFuncAttributeMaxDynamicSharedMemorySize, SM_TOTAL);

    const int gemm_blocks = (N + 127) / 128;
    const int gather_blocks = (N * 32 + 255) / 256;
    const int EB = E0 + E1;

    // ---- CSR for both layers ----
    cudaMemsetAsync(dcnt, 0, 2 * NN * sizeof(int));
    count_both<<<(EB + 255) / 256, 256>>>(ei0, ei1, E0, E1, dcnt);
    scan_both<<<2, 1024>>>(dcnt, drp, drp2, N);
    fill_both<<<(EB + 255) / 256, 256>>>(ei0, ei1, E0, E1, drp2, dcsr);

    // ---- layer 0 ----
    gather_kernel<<<gather_blocks, 256>>>(embs, drp, dcsr, dagg, N);
    fused_tc<<<gemm_blocks, 256, SM_TOTAL>>>(embs, dagg, wl0, wr0, b0,
                                             dx1, N, 1);

    // ---- layer 1 ----
    gather_kernel<<<gather_blocks, 256>>>(dx1, drp + (NN + 1), dcsr + NE,
                                          dagg, N);
    fused_tc<<<gemm_blocks, 256, SM_TOTAL>>>(dx1, dagg, wl1, wr1, b1,
                                             out, N, 0);
}